// round 13
// baseline (speedup 1.0000x reference)
#include <cuda_runtime.h>
#include <cuda_fp16.h>
#include <cstdint>
#include <math.h>

// Problem constants
#define B_SZ 1024
#define D_SZ 512
#define H_SZ 1024
#define T_SZ 8
#define E_SZ 18

// ==================== PTX helpers ====================
__device__ __forceinline__ uint32_t smem_to_u32(const void* p) {
    uint32_t a;
    asm("{ .reg .u64 t; cvta.to.shared.u64 t, %1; cvt.u32.u64 %0, t; }" : "=r"(a) : "l"(p));
    return a;
}
#define CP_ASYNC16(dst, src) \
    asm volatile("cp.async.cg.shared.global [%0], [%1], 16;" :: "r"(dst), "l"(src))
#define CP_COMMIT() asm volatile("cp.async.commit_group;" ::: "memory")
#define CP_WAIT1()  asm volatile("cp.async.wait_group 1;" ::: "memory")

#define LDSM_X4(r, a) \
    asm volatile("ldmatrix.sync.aligned.m8n8.x4.shared.b16 {%0,%1,%2,%3}, [%4];" \
        : "=r"((r)[0]), "=r"((r)[1]), "=r"((r)[2]), "=r"((r)[3]) : "r"(a))
#define LDSM_X4T(r, a) \
    asm volatile("ldmatrix.sync.aligned.m8n8.x4.trans.shared.b16 {%0,%1,%2,%3}, [%4];" \
        : "=r"((r)[0]), "=r"((r)[1]), "=r"((r)[2]), "=r"((r)[3]) : "r"(a))

// f16 mma, fp32 accumulate
#define MMA16816H(c, a, b0, b1) \
    asm volatile("mma.sync.aligned.m16n8k16.row.col.f32.f16.f16.f32 " \
        "{%0,%1,%2,%3}, {%4,%5,%6,%7}, {%8,%9}, {%0,%1,%2,%3};" \
        : "+f"((c)[0]), "+f"((c)[1]), "+f"((c)[2]), "+f"((c)[3]) \
        : "r"((a)[0]), "r"((a)[1]), "r"((a)[2]), "r"((a)[3]), "r"(b0), "r"(b1))

// ==================== scratch (static device globals) ====================
__device__ __half g_xh [B_SZ * 9 * D_SZ];
#define WT_ONE (E_SZ * H_SZ * D_SZ)            // 9,437,184 elems per weight tensor
__device__ __half g_w[4 * WT_ONE];             // (E,K,N) native layout fp16
__device__ __half g_h1 [B_SZ * E_SZ * H_SZ];
__device__ float  g_eo [B_SZ * E_SZ * D_SZ];
__device__ float  g_x1 [B_SZ * 9 * D_SZ];
__device__ __half g_x1h[B_SZ * 9 * D_SZ];

// ==================== prep: fp32 -> fp16 convert, simple (for x) ====================
__global__ __launch_bounds__(256)
void conv_f32h(const float* __restrict__ X, __half* __restrict__ H, int n4)
{
    int i0 = (blockIdx.x * blockDim.x + threadIdx.x) * 2;
    #pragma unroll
    for (int u = 0; u < 2; ++u) {
        int i = i0 + u;
        if (i >= n4) return;
        float4 v = ((const float4*)X)[i];
        __half2 hp0 = {__float2half_rn(v.x), __float2half_rn(v.y)};
        __half2 hp1 = {__float2half_rn(v.z), __float2half_rn(v.w)};
        ((__half2*)H)[2*i]   = hp0;
        ((__half2*)H)[2*i+1] = hp1;
    }
}

// ==================== prep: single-tensor weight convert (W1_0 only) ====================
__global__ __launch_bounds__(256)
void conv_one(const float* __restrict__ src, __half* __restrict__ dst, int n8)
{
    int i0 = (blockIdx.x * blockDim.x + threadIdx.x) * 4;
    float4 v[8];
    #pragma unroll
    for (int u = 0; u < 4; ++u) {
        int i = i0 + u;
        if (i < n8) {
            v[2*u]   = ((const float4*)src)[2*i];
            v[2*u+1] = ((const float4*)src)[2*i + 1];
        }
    }
    #pragma unroll
    for (int u = 0; u < 4; ++u) {
        int i = i0 + u;
        if (i >= n8) return;
        __half2 a = {__float2half_rn(v[2*u].x), __float2half_rn(v[2*u].y)};
        __half2 b = {__float2half_rn(v[2*u].z), __float2half_rn(v[2*u].w)};
        __half2 c = {__float2half_rn(v[2*u+1].x), __float2half_rn(v[2*u+1].y)};
        __half2 d = {__float2half_rn(v[2*u+1].z), __float2half_rn(v[2*u+1].w)};
        uint4 o;
        o.x = *(uint32_t*)&a; o.y = *(uint32_t*)&b;
        o.z = *(uint32_t*)&c; o.w = *(uint32_t*)&d;
        ((uint4*)dst)[i] = o;
    }
}

// ==================== GEMM: mma.sync fp16, 64x32 warp tiles, 3 CTAs/SM ====================
// CTA tile 128x64, 4 warps (2m x 2n), BK=64, 3-stage cp.async.
// CONV=1: grid is (16, 11, 18); CTAs with blockIdx.y >= 8 convert 3 weight tensors.
#define STAGE_BYTES 24576
#define GEMM_SMEM   (1024 + 3 * STAGE_BYTES)

template<int EPI_F16, int CONV>
__global__ __launch_bounds__(128, 3)
void gemm_mma1(const __half* __restrict__ Ah,
               const __half* __restrict__ Bw,
               const float* __restrict__ bias,
               float* __restrict__ Cf, __half* __restrict__ Ch,
               int K, int a_mul, int a_shift, int Ntot,
               const float* __restrict__ C0, const float* __restrict__ C1,
               const float* __restrict__ C2, __half* __restrict__ Cd)
{
    if (CONV && blockIdx.y >= 8) {
        // converter CTA: 864 total = 3 tensors x 288 CTAs; 32 chunks (16B) per thread.
        int c = blockIdx.z * 48 + (blockIdx.y - 8) * 16 + blockIdx.x;  // [0, 864)
        int t = c / 288, local = c - t * 288;
        const float* src = (t == 0) ? C0 : (t == 1) ? C1 : C2;
        __half* dst = Cd + (size_t)t * WT_ONE;
        int base = local * 128 + threadIdx.x;                          // [0, 36864)
        #pragma unroll 4
        for (int j = 0; j < 32; ++j) {
            int i = j * 36864 + base;                                  // coalesced per warp
            float4 v0 = ((const float4*)src)[2*i];
            float4 v1 = ((const float4*)src)[2*i + 1];
            __half2 a = {__float2half_rn(v0.x), __float2half_rn(v0.y)};
            __half2 b = {__float2half_rn(v0.z), __float2half_rn(v0.w)};
            __half2 cc = {__float2half_rn(v1.x), __float2half_rn(v1.y)};
            __half2 d = {__float2half_rn(v1.z), __float2half_rn(v1.w)};
            uint4 o;
            o.x = *(uint32_t*)&a; o.y = *(uint32_t*)&b;
            o.z = *(uint32_t*)&cc; o.w = *(uint32_t*)&d;
            ((uint4*)dst)[i] = o;
        }
        return;
    }

    extern __shared__ char smem[];
    const uint32_t su = smem_to_u32(smem);
    const int tid  = threadIdx.x;
    const int wid  = tid >> 5;
    const int lane = tid & 31;
    const int e  = blockIdx.z;
    const int m0 = blockIdx.y * 128;
    const int n0 = blockIdx.x * 64;
    const int warp_m = wid & 1;     // 2 warps in m (64 rows each)
    const int warp_n = wid >> 1;    // 2 warps in n (32 cols each)
    const int esel = e >> a_shift;

    if (tid < 64)
        ((float*)smem)[tid] = bias[(size_t)e * Ntot + n0 + tid];

    // ---- stage loader (cp.async), BK=64 ----
    // A tile (@0):     128 rows x 64 k (128B rows, 8 chunks), swizzle ac ^ (row&7)
    // B tile (@16384): 64 k-rows x 64 n (128B rows, 8 chunks), swizzle nc ^ (krow&7)
    auto load_stage = [&](int s, int k0) {
        uint32_t st = su + 1024 + s * STAGE_BYTES;
        #pragma unroll
        for (int t = 0; t < 8; ++t) {
            int idx = tid + t * 128;
            int arow = idx >> 3, ac = idx & 7;
            size_t aoff = ((size_t)(m0 + arow) * a_mul + esel) * K + k0 + ac * 8;
            uint32_t ad = arow * 128 + ((ac ^ (arow & 7)) << 4);
            CP_ASYNC16(st + ad, Ah + aoff);
        }
        #pragma unroll
        for (int t = 0; t < 4; ++t) {
            int idx = tid + t * 128;
            int krow = idx >> 3, nc = idx & 7;
            size_t boff = ((size_t)e * K + k0 + krow) * Ntot + n0 + nc * 8;
            uint32_t bd = krow * 128 + ((nc ^ (krow & 7)) << 4);
            CP_ASYNC16(st + 16384 + bd, Bw + boff);
        }
        CP_COMMIT();
    };

    float c[4][4][4];
    #pragma unroll
    for (int i = 0; i < 4; i++)
        #pragma unroll
        for (int j = 0; j < 4; j++)
            #pragma unroll
            for (int q = 0; q < 4; q++) c[i][j][q] = 0.f;

    const int nk = K >> 6;
    load_stage(0, 0);
    load_stage(1, 64);

    const int a_rl   = (lane & 7) + ((lane >> 3) & 1) * 8;
    const int a_kc_h = lane >> 4;
    const int b_kl   = (lane & 7) + ((lane >> 3) & 1) * 8;
    const int b_nc_h = lane >> 4;

    int s = 0;
    for (int cIt = 0; cIt < nk; ++cIt) {
        CP_WAIT1();            // this thread's stage-cIt copies done
        __syncthreads();       // ALL threads' copies visible; prior compute drained
        if (cIt + 2 < nk) {
            int sn = s + 2;
            if (sn >= 3) sn -= 3;
            load_stage(sn, (cIt + 2) << 6);
        } else {
            CP_COMMIT();
        }

        uint32_t st = su + 1024 + s * STAGE_BYTES;
        #pragma unroll
        for (int ks = 0; ks < 4; ++ks) {
            uint32_t ah[4][4];
            #pragma unroll
            for (int mi = 0; mi < 4; ++mi) {
                int row = warp_m * 64 + mi * 16 + a_rl;
                int kc  = ks * 2 + a_kc_h;
                uint32_t ad = st + row * 128 + ((kc ^ (row & 7)) << 4);
                LDSM_X4(ah[mi], ad);
            }
            uint32_t bw[2][4];
            #pragma unroll
            for (int ni = 0; ni < 2; ++ni) {
                int krow = ks * 16 + b_kl;
                int nc   = warp_n * 4 + ni * 2 + b_nc_h;
                uint32_t bd = st + 16384 + krow * 128 + ((nc ^ (krow & 7)) << 4);
                LDSM_X4T(bw[ni], bd);
            }
            #pragma unroll
            for (int mi = 0; mi < 4; ++mi)
                #pragma unroll
                for (int ni = 0; ni < 2; ++ni)
                    #pragma unroll
                    for (int h = 0; h < 2; ++h)
                        MMA16816H(c[mi][ni * 2 + h], ah[mi], bw[ni][h * 2], bw[ni][h * 2 + 1]);
        }
        s = (s == 2) ? 0 : s + 1;
    }

    // ---- epilogue ----
    const float* bs = (const float*)smem;
    #pragma unroll
    for (int mi = 0; mi < 4; ++mi) {
        int r0 = m0 + warp_m * 64 + mi * 16 + (lane >> 2);
        #pragma unroll
        for (int h2 = 0; h2 < 2; ++h2) {
            int row = r0 + h2 * 8;
            size_t cbase = ((size_t)row * E_SZ + e) * Ntot;
            #pragma unroll
            for (int nj = 0; nj < 4; ++nj) {
                int col = warp_n * 32 + nj * 8 + (lane & 3) * 2;
                float v0 = c[mi][nj][h2 * 2]     + bs[col];
                float v1 = c[mi][nj][h2 * 2 + 1] + bs[col + 1];
                if (EPI_F16) {
                    v0 = fmaxf(v0, 0.f); v1 = fmaxf(v1, 0.f);
                    __half2 hp = {__float2half_rn(v0), __float2half_rn(v1)};
                    *(uint32_t*)(Ch + cbase + n0 + col) = *(uint32_t*)&hp;
                } else {
                    *(float2*)(Cf + cbase + n0 + col) = make_float2(v0, v1);
                }
            }
        }
    }
}

// ==================== fused gate + combine ====================
__global__ __launch_bounds__(256)
void fused_gate_combine(const float* __restrict__ x,
                        const float* __restrict__ Wg,
                        const float* __restrict__ bg,
                        const float* __restrict__ sew_task,   // (8,2,2)
                        const float* __restrict__ sew_shared, // (1,2)
                        const float* __restrict__ EO,
                        float* __restrict__ OUT,
                        __half* __restrict__ OH,
                        int M, int layer)
{
    __shared__ float xs[9 * D_SZ];
    __shared__ float lg[9 * E_SZ];
    __shared__ float gs[9 * E_SZ];
    const int b   = blockIdx.x;
    const int tid = threadIdx.x;

    for (int i = tid; i < M * D_SZ; i += 256)
        xs[i] = x[(size_t)b * 9 * D_SZ + i];
    __syncthreads();

    if (tid < M * E_SZ) {
        int m = tid / E_SZ, e = tid - m * E_SZ;
        const float* xr = xs + m * D_SZ;
        const float* w  = Wg + (size_t)m * D_SZ * E_SZ + e;
        float a0 = 0.f, a1 = 0.f;
        #pragma unroll 4
        for (int k = 0; k < D_SZ; k += 2) {
            a0 += xr[k]     * w[(size_t)k * E_SZ];
            a1 += xr[k + 1] * w[(size_t)(k + 1) * E_SZ];
        }
        lg[tid] = a0 + a1 + bg[m * E_SZ + e];
    }
    __syncthreads();

    if (tid < M) {
        float mx = -3.4e38f;
        #pragma unroll
        for (int e = 0; e < E_SZ; e++) mx = fmaxf(mx, lg[tid * E_SZ + e]);
        float sum = 0.f;
        float ex[E_SZ];
        #pragma unroll
        for (int e = 0; e < E_SZ; e++) { ex[e] = expf(lg[tid * E_SZ + e] - mx); sum += ex[e]; }
        float inv = 1.f / sum;
        #pragma unroll
        for (int e = 0; e < E_SZ; e++) gs[tid * E_SZ + e] = ex[e] * inv;
        if (layer == 0) {
            if (tid < T_SZ) {
                gs[tid * E_SZ + 2 * tid]     += sew_task[tid * 4 + 0];
                gs[tid * E_SZ + 2 * tid + 1] += sew_task[tid * 4 + 1];
            } else {
                gs[tid * E_SZ + 16] += sew_shared[0];
                gs[tid * E_SZ + 17] += sew_shared[1];
            }
        } else {
            gs[tid * E_SZ + 2 * tid]     += sew_task[tid * 4 + 2];
            gs[tid * E_SZ + 2 * tid + 1] += sew_task[tid * 4 + 3];
        }
    }
    __syncthreads();

    const float* eo = EO + (size_t)b * E_SZ * D_SZ;
    for (int d = tid; d < D_SZ; d += 256) {
        float ev[E_SZ];
        #pragma unroll
        for (int e2 = 0; e2 < E_SZ; e2++)
            ev[e2] = eo[(size_t)e2 * D_SZ + d];
        for (int m = 0; m < M; m++) {
            float s = 0.f;
            #pragma unroll
            for (int e2 = 0; e2 < E_SZ; e2++)
                s += gs[m * E_SZ + e2] * ev[e2];
            if (OH) {
                size_t o = ((size_t)b * 9 + m) * D_SZ + d;
                OUT[o] = s;
                OH[o]  = __float2half_rn(s);
            } else {
                OUT[((size_t)b * M + m) * D_SZ + d] = s;
            }
        }
    }
}

// ==================== launcher ====================
extern "C" void kernel_launch(void* const* d_in, const int* in_sizes, int n_in,
                              void* d_out, int out_size)
{
    const float* x_in  = (const float*)d_in[0];
    const float* W1_0  = (const float*)d_in[1];
    const float* b1_0  = (const float*)d_in[2];
    const float* W2_0  = (const float*)d_in[3];
    const float* b2_0  = (const float*)d_in[4];
    const float* Wg_0  = (const float*)d_in[5];
    const float* bg_0  = (const float*)d_in[6];
    const float* W1_1  = (const float*)d_in[7];
    const float* b1_1  = (const float*)d_in[8];
    const float* W2_1  = (const float*)d_in[9];
    const float* b2_1  = (const float*)d_in[10];
    const float* Wg_1  = (const float*)d_in[11];
    const float* bg_1  = (const float*)d_in[12];
    const float* sewt  = (const float*)d_in[13];
    const float* sews  = (const float*)d_in[14];
    float* out = (float*)d_out;

    __half *xh, *w, *h1, *x1h;
    float *eo, *x1;
    cudaGetSymbolAddress((void**)&xh,  g_xh);
    cudaGetSymbolAddress((void**)&w,   g_w);
    cudaGetSymbolAddress((void**)&h1,  g_h1);
    cudaGetSymbolAddress((void**)&eo,  g_eo);
    cudaGetSymbolAddress((void**)&x1,  g_x1);
    cudaGetSymbolAddress((void**)&x1h, g_x1h);

    cudaFuncSetAttribute(gemm_mma1<1,1>, cudaFuncAttributeMaxDynamicSharedMemorySize, GEMM_SMEM);
    cudaFuncSetAttribute(gemm_mma1<1,0>, cudaFuncAttributeMaxDynamicSharedMemorySize, GEMM_SMEM);
    cudaFuncSetAttribute(gemm_mma1<0,0>, cudaFuncAttributeMaxDynamicSharedMemorySize, GEMM_SMEM);

    // ---- prep: only x and W1_0 on the critical path ----
    int n4x = B_SZ * 9 * D_SZ / 4;
    conv_f32h<<<(n4x/2 + 255) / 256, 256>>>(x_in, xh, n4x);
    int n8w = WT_ONE / 8;
    conv_one<<<(n8w/4 + 255) / 256, 256>>>(W1_0, w + 0*WT_ONE, n8w);

    dim3 g1c(H_SZ / 64, 11, E_SZ);           // (16, 11, 18): y<8 gemm, y>=8 convert 3 tensors
    dim3 g1(H_SZ / 64, B_SZ / 128, E_SZ);    // (16, 8, 18)
    dim3 g2(D_SZ / 64, B_SZ / 128, E_SZ);    // (8, 8, 18)

    // ---- layer 0 (gemm1 also converts the remaining 3 weight tensors, overlapped) ----
    gemm_mma1<1,1><<<g1c, 128, GEMM_SMEM>>>(xh, w + 0*WT_ONE, b1_0,
                                            nullptr, h1, D_SZ, 9, 1, H_SZ,
                                            W2_0, W1_1, W2_1, w + 1*WT_ONE);
    gemm_mma1<0,0><<<g2, 128, GEMM_SMEM>>>(h1, w + 1*WT_ONE, b2_0,
                                           eo, nullptr, H_SZ, E_SZ, 0, D_SZ,
                                           nullptr, nullptr, nullptr, nullptr);
    fused_gate_combine<<<B_SZ, 256>>>(x_in, Wg_0, bg_0, sewt, sews, eo, x1, x1h, 9, 0);

    // ---- layer 1 ----
    gemm_mma1<1,0><<<g1, 128, GEMM_SMEM>>>(x1h, w + 2*WT_ONE, b1_1,
                                           nullptr, h1, D_SZ, 9, 1, H_SZ,
                                           nullptr, nullptr, nullptr, nullptr);
    gemm_mma1<0,0><<<g2, 128, GEMM_SMEM>>>(h1, w + 3*WT_ONE, b2_1,
                                           eo, nullptr, H_SZ, E_SZ, 0, D_SZ,
                                           nullptr, nullptr, nullptr, nullptr);
    fused_gate_combine<<<B_SZ, 256>>>(x1, Wg_1, bg_1, sewt, sews, eo, out, nullptr, 8, 1);
}

// round 14
// speedup vs baseline: 1.0609x; 1.0609x over previous
#include <cuda_runtime.h>
#include <cuda_fp16.h>
#include <cstdint>
#include <math.h>

// Problem constants
#define B_SZ 1024
#define D_SZ 512
#define H_SZ 1024
#define T_SZ 8
#define E_SZ 18

// ==================== PTX helpers ====================
__device__ __forceinline__ uint32_t smem_to_u32(const void* p) {
    uint32_t a;
    asm("{ .reg .u64 t; cvta.to.shared.u64 t, %1; cvt.u32.u64 %0, t; }" : "=r"(a) : "l"(p));
    return a;
}
#define CP_ASYNC16(dst, src) \
    asm volatile("cp.async.cg.shared.global [%0], [%1], 16;" :: "r"(dst), "l"(src))
#define CP_COMMIT() asm volatile("cp.async.commit_group;" ::: "memory")
#define CP_WAIT1()  asm volatile("cp.async.wait_group 1;" ::: "memory")

#define LDSM_X4(r, a) \
    asm volatile("ldmatrix.sync.aligned.m8n8.x4.shared.b16 {%0,%1,%2,%3}, [%4];" \
        : "=r"((r)[0]), "=r"((r)[1]), "=r"((r)[2]), "=r"((r)[3]) : "r"(a))
#define LDSM_X4T(r, a) \
    asm volatile("ldmatrix.sync.aligned.m8n8.x4.trans.shared.b16 {%0,%1,%2,%3}, [%4];" \
        : "=r"((r)[0]), "=r"((r)[1]), "=r"((r)[2]), "=r"((r)[3]) : "r"(a))

// f16 mma, fp32 accumulate
#define MMA16816H(c, a, b0, b1) \
    asm volatile("mma.sync.aligned.m16n8k16.row.col.f32.f16.f16.f32 " \
        "{%0,%1,%2,%3}, {%4,%5,%6,%7}, {%8,%9}, {%0,%1,%2,%3};" \
        : "+f"((c)[0]), "+f"((c)[1]), "+f"((c)[2]), "+f"((c)[3]) \
        : "r"((a)[0]), "r"((a)[1]), "r"((a)[2]), "r"((a)[3]), "r"(b0), "r"(b1))

// ==================== scratch (static device globals) ====================
__device__ __half g_xh [B_SZ * 9 * D_SZ];
#define WT_ONE (E_SZ * H_SZ * D_SZ)            // 9,437,184 elems per weight tensor
__device__ __half g_w[4 * WT_ONE];             // (E,K,N) native layout fp16
__device__ __half g_h1 [B_SZ * E_SZ * H_SZ];
__device__ __half g_eo [B_SZ * E_SZ * D_SZ];   // expert outputs, fp16
__device__ __half g_x1h[B_SZ * 9 * D_SZ];      // layer-1 input, fp16 (pitch-9)

// ==================== prep: fp32 -> fp16 convert, simple (for x) ====================
__global__ __launch_bounds__(256)
void conv_f32h(const float* __restrict__ X, __half* __restrict__ H, int n4)
{
    int i0 = (blockIdx.x * blockDim.x + threadIdx.x) * 2;
    #pragma unroll
    for (int u = 0; u < 2; ++u) {
        int i = i0 + u;
        if (i >= n4) return;
        float4 v = ((const float4*)X)[i];
        __half2 hp0 = {__float2half_rn(v.x), __float2half_rn(v.y)};
        __half2 hp1 = {__float2half_rn(v.z), __float2half_rn(v.w)};
        ((__half2*)H)[2*i]   = hp0;
        ((__half2*)H)[2*i+1] = hp1;
    }
}

// ==================== prep: single-tensor weight convert (W1_0 only) ====================
__global__ __launch_bounds__(256)
void conv_one(const float* __restrict__ src, __half* __restrict__ dst, int n8)
{
    int i0 = (blockIdx.x * blockDim.x + threadIdx.x) * 4;
    float4 v[8];
    #pragma unroll
    for (int u = 0; u < 4; ++u) {
        int i = i0 + u;
        if (i < n8) {
            v[2*u]   = ((const float4*)src)[2*i];
            v[2*u+1] = ((const float4*)src)[2*i + 1];
        }
    }
    #pragma unroll
    for (int u = 0; u < 4; ++u) {
        int i = i0 + u;
        if (i >= n8) return;
        __half2 a = {__float2half_rn(v[2*u].x), __float2half_rn(v[2*u].y)};
        __half2 b = {__float2half_rn(v[2*u].z), __float2half_rn(v[2*u].w)};
        __half2 c = {__float2half_rn(v[2*u+1].x), __float2half_rn(v[2*u+1].y)};
        __half2 d = {__float2half_rn(v[2*u+1].z), __float2half_rn(v[2*u+1].w)};
        uint4 o;
        o.x = *(uint32_t*)&a; o.y = *(uint32_t*)&b;
        o.z = *(uint32_t*)&c; o.w = *(uint32_t*)&d;
        ((uint4*)dst)[i] = o;
    }
}

// ==================== GEMM: mma.sync fp16, 64x64 warp tiles (R11 proven config) =======
// EPI: 1 = relu + fp16 out, 2 = fp16 out (no relu).
// CONV=1: grid is (8, 14, 18); CTAs with blockIdx.y >= 8 convert 3 weight tensors.
#define STAGE_BYTES 32768
#define GEMM_SMEM   (1024 + 3 * STAGE_BYTES)

template<int EPI, int CONV>
__global__ __launch_bounds__(128, 2)
void gemm_mma1(const __half* __restrict__ Ah,
               const __half* __restrict__ Bw,
               const float* __restrict__ bias,
               __half* __restrict__ Ch,
               int K, int a_mul, int a_shift, int Ntot,
               const float* __restrict__ C0, const float* __restrict__ C1,
               const float* __restrict__ C2, __half* __restrict__ Cd)
{
    if (CONV && blockIdx.y >= 8) {
        // converter CTA: 864 total = 3 tensors x 288 CTAs; 32 chunks (16B) per thread.
        int c = blockIdx.z * 48 + (blockIdx.y - 8) * 8 + blockIdx.x;   // [0, 864)
        int t = c / 288, local = c - t * 288;
        const float* src = (t == 0) ? C0 : (t == 1) ? C1 : C2;
        __half* dst = Cd + (size_t)t * WT_ONE;
        int base = local * 128 + threadIdx.x;                          // [0, 36864)
        #pragma unroll 4
        for (int j = 0; j < 32; ++j) {
            int i = j * 36864 + base;                                  // coalesced per warp
            float4 v0 = ((const float4*)src)[2*i];
            float4 v1 = ((const float4*)src)[2*i + 1];
            __half2 a = {__float2half_rn(v0.x), __float2half_rn(v0.y)};
            __half2 b = {__float2half_rn(v0.z), __float2half_rn(v0.w)};
            __half2 cc = {__float2half_rn(v1.x), __float2half_rn(v1.y)};
            __half2 d = {__float2half_rn(v1.z), __float2half_rn(v1.w)};
            uint4 o;
            o.x = *(uint32_t*)&a; o.y = *(uint32_t*)&b;
            o.z = *(uint32_t*)&cc; o.w = *(uint32_t*)&d;
            ((uint4*)dst)[i] = o;
        }
        return;
    }

    extern __shared__ char smem[];
    const uint32_t su = smem_to_u32(smem);
    const int tid  = threadIdx.x;
    const int wid  = tid >> 5;
    const int lane = tid & 31;
    const int e  = blockIdx.z;
    const int m0 = blockIdx.y * 128;
    const int n0 = blockIdx.x * 128;
    const int warp_m = wid & 1;     // 2 warps in m (64 rows each)
    const int warp_n = wid >> 1;    // 2 warps in n (64 cols each)
    const int esel = e >> a_shift;

    if (tid < 128)
        ((float*)smem)[tid] = bias[(size_t)e * Ntot + n0 + tid];

    auto load_stage = [&](int s, int k0) {
        uint32_t st = su + 1024 + s * STAGE_BYTES;
        #pragma unroll
        for (int t = 0; t < 8; ++t) {
            int idx = tid + t * 128;
            int arow = idx >> 3, ac = idx & 7;
            size_t aoff = ((size_t)(m0 + arow) * a_mul + esel) * K + k0 + ac * 8;
            uint32_t ad = arow * 128 + ((ac ^ (arow & 7)) << 4);
            CP_ASYNC16(st + ad, Ah + aoff);
            int krow = idx >> 4, nc = idx & 15;
            size_t boff = ((size_t)e * K + k0 + krow) * Ntot + n0 + nc * 8;
            uint32_t bd = krow * 256 + ((nc ^ (krow & 7)) << 4);
            CP_ASYNC16(st + 16384 + bd, Bw + boff);
        }
        CP_COMMIT();
    };

    float c[4][8][4];
    #pragma unroll
    for (int i = 0; i < 4; i++)
        #pragma unroll
        for (int j = 0; j < 8; j++)
            #pragma unroll
            for (int q = 0; q < 4; q++) c[i][j][q] = 0.f;

    const int nk = K >> 6;
    load_stage(0, 0);
    load_stage(1, 64);

    const int a_rl   = (lane & 7) + ((lane >> 3) & 1) * 8;
    const int a_kc_h = lane >> 4;
    const int b_kl   = (lane & 7) + ((lane >> 3) & 1) * 8;
    const int b_nc_h = lane >> 4;

    int s = 0;
    for (int cIt = 0; cIt < nk; ++cIt) {
        CP_WAIT1();            // this thread's stage-cIt copies done
        __syncthreads();       // ALL threads' copies visible; prior compute drained
        if (cIt + 2 < nk) {
            int sn = s + 2;
            if (sn >= 3) sn -= 3;
            load_stage(sn, (cIt + 2) << 6);
        } else {
            CP_COMMIT();
        }

        uint32_t st = su + 1024 + s * STAGE_BYTES;
        #pragma unroll
        for (int ks = 0; ks < 4; ++ks) {
            uint32_t ah[4][4];
            #pragma unroll
            for (int mi = 0; mi < 4; ++mi) {
                int row = warp_m * 64 + mi * 16 + a_rl;
                int kc  = ks * 2 + a_kc_h;
                uint32_t ad = st + row * 128 + ((kc ^ (row & 7)) << 4);
                LDSM_X4(ah[mi], ad);
            }
            uint32_t bw[4][4];
            #pragma unroll
            for (int ni = 0; ni < 4; ++ni) {
                int krow = ks * 16 + b_kl;
                int nc   = warp_n * 8 + ni * 2 + b_nc_h;
                uint32_t bd = st + 16384 + krow * 256 + ((nc ^ (krow & 7)) << 4);
                LDSM_X4T(bw[ni], bd);
            }
            #pragma unroll
            for (int mi = 0; mi < 4; ++mi)
                #pragma unroll
                for (int ni = 0; ni < 4; ++ni)
                    #pragma unroll
                    for (int h = 0; h < 2; ++h)
                        MMA16816H(c[mi][ni * 2 + h], ah[mi], bw[ni][h * 2], bw[ni][h * 2 + 1]);
        }
        s = (s == 2) ? 0 : s + 1;
    }

    // ---- epilogue: bias (+relu), fp16 out ----
    const float* bs = (const float*)smem;
    #pragma unroll
    for (int mi = 0; mi < 4; ++mi) {
        int r0 = m0 + warp_m * 64 + mi * 16 + (lane >> 2);
        #pragma unroll
        for (int h2 = 0; h2 < 2; ++h2) {
            int row = r0 + h2 * 8;
            size_t cbase = ((size_t)row * E_SZ + e) * Ntot;
            #pragma unroll
            for (int nj = 0; nj < 8; ++nj) {
                int col = warp_n * 64 + nj * 8 + (lane & 3) * 2;
                float v0 = c[mi][nj][h2 * 2]     + bs[col];
                float v1 = c[mi][nj][h2 * 2 + 1] + bs[col + 1];
                if (EPI == 1) { v0 = fmaxf(v0, 0.f); v1 = fmaxf(v1, 0.f); }
                __half2 hp = {__float2half_rn(v0), __float2half_rn(v1)};
                *(uint32_t*)(Ch + cbase + n0 + col) = *(uint32_t*)&hp;
            }
        }
    }
}

// ==================== fused gate + combine (fp16 EO, fp16 chain) ====================
// Gate input: xf (fp32) if non-null, else xh (fp16). Output: OUT fp32 (final) or
// OH fp16 (layer chain). Thread handles d0 = 2*tid (covers D=512 with 256 threads).
__global__ __launch_bounds__(256)
void fused_gate_combine(const float* __restrict__ xf,
                        const __half* __restrict__ xhp,
                        const float* __restrict__ Wg,
                        const float* __restrict__ bg,
                        const float* __restrict__ sew_task,   // (8,2,2)
                        const float* __restrict__ sew_shared, // (1,2)
                        const __half* __restrict__ EO,
                        float* __restrict__ OUT,
                        __half* __restrict__ OH,
                        int M, int layer)
{
    __shared__ float xs[9 * D_SZ];
    __shared__ float lg[9 * E_SZ];
    __shared__ float gs[9 * E_SZ];
    const int b   = blockIdx.x;
    const int tid = threadIdx.x;

    if (xf) {
        for (int i = tid; i < M * D_SZ; i += 256)
            xs[i] = xf[(size_t)b * 9 * D_SZ + i];
    } else {
        const __half2* xr = (const __half2*)(xhp + (size_t)b * 9 * D_SZ);
        for (int i = tid; i < M * D_SZ / 2; i += 256) {
            float2 v = __half22float2(xr[i]);
            xs[2*i] = v.x; xs[2*i + 1] = v.y;
        }
    }
    __syncthreads();

    if (tid < M * E_SZ) {
        int m = tid / E_SZ, e = tid - m * E_SZ;
        const float* xr = xs + m * D_SZ;
        const float* w  = Wg + (size_t)m * D_SZ * E_SZ + e;
        float a0 = 0.f, a1 = 0.f;
        #pragma unroll 4
        for (int k = 0; k < D_SZ; k += 2) {
            a0 += xr[k]     * w[(size_t)k * E_SZ];
            a1 += xr[k + 1] * w[(size_t)(k + 1) * E_SZ];
        }
        lg[tid] = a0 + a1 + bg[m * E_SZ + e];
    }
    __syncthreads();

    if (tid < M) {
        float mx = -3.4e38f;
        #pragma unroll
        for (int e = 0; e < E_SZ; e++) mx = fmaxf(mx, lg[tid * E_SZ + e]);
        float sum = 0.f;
        float ex[E_SZ];
        #pragma unroll
        for (int e = 0; e < E_SZ; e++) { ex[e] = expf(lg[tid * E_SZ + e] - mx); sum += ex[e]; }
        float inv = 1.f / sum;
        #pragma unroll
        for (int e = 0; e < E_SZ; e++) gs[tid * E_SZ + e] = ex[e] * inv;
        if (layer == 0) {
            if (tid < T_SZ) {
                gs[tid * E_SZ + 2 * tid]     += sew_task[tid * 4 + 0];
                gs[tid * E_SZ + 2 * tid + 1] += sew_task[tid * 4 + 1];
            } else {
                gs[tid * E_SZ + 16] += sew_shared[0];
                gs[tid * E_SZ + 17] += sew_shared[1];
            }
        } else {
            gs[tid * E_SZ + 2 * tid]     += sew_task[tid * 4 + 2];
            gs[tid * E_SZ + 2 * tid + 1] += sew_task[tid * 4 + 3];
        }
    }
    __syncthreads();

    // combine: d0 = 2*tid, half2 loads (coalesced)
    const __half* eo = EO + (size_t)b * E_SZ * D_SZ;
    const int d0 = 2 * tid;
    float evx[E_SZ], evy[E_SZ];
    #pragma unroll
    for (int e2 = 0; e2 < E_SZ; e2++) {
        float2 v = __half22float2(*(const __half2*)(eo + (size_t)e2 * D_SZ + d0));
        evx[e2] = v.x; evy[e2] = v.y;
    }
    for (int m = 0; m < M; m++) {
        float s0 = 0.f, s1 = 0.f;
        #pragma unroll
        for (int e2 = 0; e2 < E_SZ; e2++) {
            float g = gs[m * E_SZ + e2];
            s0 += g * evx[e2];
            s1 += g * evy[e2];
        }
        if (OUT) {
            *(float2*)(OUT + ((size_t)b * M + m) * D_SZ + d0) = make_float2(s0, s1);
        } else {
            __half2 hp = {__float2half_rn(s0), __float2half_rn(s1)};
            *(__half2*)(OH + ((size_t)b * 9 + m) * D_SZ + d0) = hp;
        }
    }
}

// ==================== launcher ====================
extern "C" void kernel_launch(void* const* d_in, const int* in_sizes, int n_in,
                              void* d_out, int out_size)
{
    const float* x_in  = (const float*)d_in[0];
    const float* W1_0  = (const float*)d_in[1];
    const float* b1_0  = (const float*)d_in[2];
    const float* W2_0  = (const float*)d_in[3];
    const float* b2_0  = (const float*)d_in[4];
    const float* Wg_0  = (const float*)d_in[5];
    const float* bg_0  = (const float*)d_in[6];
    const float* W1_1  = (const float*)d_in[7];
    const float* b1_1  = (const float*)d_in[8];
    const float* W2_1  = (const float*)d_in[9];
    const float* b2_1  = (const float*)d_in[10];
    const float* Wg_1  = (const float*)d_in[11];
    const float* bg_1  = (const float*)d_in[12];
    const float* sewt  = (const float*)d_in[13];
    const float* sews  = (const float*)d_in[14];
    float* out = (float*)d_out;

    __half *xh, *w, *h1, *eo, *x1h;
    cudaGetSymbolAddress((void**)&xh,  g_xh);
    cudaGetSymbolAddress((void**)&w,   g_w);
    cudaGetSymbolAddress((void**)&h1,  g_h1);
    cudaGetSymbolAddress((void**)&eo,  g_eo);
    cudaGetSymbolAddress((void**)&x1h, g_x1h);

    cudaFuncSetAttribute(gemm_mma1<1,1>, cudaFuncAttributeMaxDynamicSharedMemorySize, GEMM_SMEM);
    cudaFuncSetAttribute(gemm_mma1<1,0>, cudaFuncAttributeMaxDynamicSharedMemorySize, GEMM_SMEM);
    cudaFuncSetAttribute(gemm_mma1<2,0>, cudaFuncAttributeMaxDynamicSharedMemorySize, GEMM_SMEM);

    // ---- prep: only x and W1_0 on the critical path ----
    int n4x = B_SZ * 9 * D_SZ / 4;
    conv_f32h<<<(n4x/2 + 255) / 256, 256>>>(x_in, xh, n4x);
    int n8w = WT_ONE / 8;
    conv_one<<<(n8w/4 + 255) / 256, 256>>>(W1_0, w + 0*WT_ONE, n8w);

    dim3 g1c(H_SZ / 128, 14, E_SZ);          // (8, 14, 18): y<8 gemm, y>=8 convert 3 tensors
    dim3 g1(H_SZ / 128, B_SZ / 128, E_SZ);   // (8, 8, 18)
    dim3 g2(D_SZ / 128, B_SZ / 128, E_SZ);   // (4, 8, 18)

    // ---- layer 0 (gemm1 also converts the remaining 3 weight tensors, overlapped) ----
    gemm_mma1<1,1><<<g1c, 128, GEMM_SMEM>>>(xh, w + 0*WT_ONE, b1_0, h1,
                                            D_SZ, 9, 1, H_SZ,
                                            W2_0, W1_1, W2_1, w + 1*WT_ONE);
    gemm_mma1<2,0><<<g2, 128, GEMM_SMEM>>>(h1, w + 1*WT_ONE, b2_0, eo,
                                           H_SZ, E_SZ, 0, D_SZ,
                                           nullptr, nullptr, nullptr, nullptr);
    fused_gate_combine<<<B_SZ, 256>>>(x_in, nullptr, Wg_0, bg_0, sewt, sews,
                                      eo, nullptr, x1h, 9, 0);

    // ---- layer 1 ----
    gemm_mma1<1,0><<<g1, 128, GEMM_SMEM>>>(x1h, w + 2*WT_ONE, b1_1, h1,
                                           D_SZ, 9, 1, H_SZ,
                                           nullptr, nullptr, nullptr, nullptr);
    gemm_mma1<2,0><<<g2, 128, GEMM_SMEM>>>(h1, w + 3*WT_ONE, b2_1, eo,
                                           H_SZ, E_SZ, 0, D_SZ,
                                           nullptr, nullptr, nullptr, nullptr);
    fused_gate_combine<<<B_SZ, 256>>>(nullptr, x1h, Wg_1, bg_1, sewt, sews,
                                      eo, out, nullptr, 8, 1);
}